// round 15
// baseline (speedup 1.0000x reference)
#include <cuda_runtime.h>
#include <cstdint>

#define BATCH   4
#define ORIG_   256
#define NORIG   (ORIG_*ORIG_)     // 65536
#define DOWN_   128
#define NDOWN   (DOWN_*DOWN_)     // 16384
#define FEAT    256
#define TILE_M  64
#define THREADS 256
#define KCH     16
#define NCHUNK  16
#define STAGES  3

// SMEM layout (floats)
#define A_STRIDE 20
#define W_STRIDE 264              // k-major W: conflict-free scalar B-frag loads
#define A_BUF    (TILE_M*A_STRIDE)        // 1280
#define W_BUF    (KCH*W_STRIDE)           // 4224
#define OFF_W    (STAGES*A_BUF)           // 3840
#define ST_STRIDE 260                     // staging stride: divisible by 4 -> 16B-aligned rows
#define ST_FLOATS (TILE_M*ST_STRIDE)      // 16640
#define OFF_G   ST_FLOATS                 // 16640 (>= STAGES*(A_BUF+W_BUF) = 16512)
#define OFF_B   (OFF_G + FEAT)            // 16896
#define OFF_RED (OFF_B + FEAT)            // 17152
#define SM_FLOATS (OFF_RED + 512)         // 17664
#define SM_BYTES  (SM_FLOATS*4)           // 70656 -> 3 CTAs/SM

__device__ float Wt_dev[2][FEAT*FEAT];   // tf32-rounded, k-major weights

__device__ __forceinline__ float tf32r(float x){
    float r; asm("cvt.rna.tf32.f32 %0, %1;" : "=f"(r) : "f"(x)); return r;
}
__device__ __forceinline__ void cpasync16(uint32_t dst, const void* src){
    asm volatile("cp.async.cg.shared.global [%0], [%1], 16;\n" :: "r"(dst), "l"(src));
}
__device__ __forceinline__ void cpcommit(){ asm volatile("cp.async.commit_group;\n" ::: "memory"); }
__device__ __forceinline__ void cpwait0(){ asm volatile("cp.async.wait_group 0;\n" ::: "memory"); }
__device__ __forceinline__ void cpwait1(){ asm volatile("cp.async.wait_group 1;\n" ::: "memory"); }

__device__ __forceinline__ void mma8(float* c, uint32_t a0, uint32_t a1, uint32_t a2,
                                     uint32_t a3, uint32_t b0, uint32_t b1){
    asm volatile(
        "mma.sync.aligned.m16n8k8.row.col.f32.tf32.tf32.f32 "
        "{%0,%1,%2,%3}, {%4,%5,%6,%7}, {%8,%9}, {%0,%1,%2,%3};\n"
        : "+f"(c[0]), "+f"(c[1]), "+f"(c[2]), "+f"(c[3])
        : "r"(a0), "r"(a1), "r"(a2), "r"(a3), "r"(b0), "r"(b1));
}

// ---- prep: Wt[k][n] = tf32_rn(W[n][k]) (512 KB total; L2-resident) ----
__global__ void prep_w(const float* __restrict__ W0, const float* __restrict__ W1){
    __shared__ float t[32][33];
    const float* W  = blockIdx.z ? W1 : W0;
    float*       Wt = Wt_dev[blockIdx.z];
    int bk = blockIdx.x*32, bn = blockIdx.y*32;
    int tx = threadIdx.x, ty = threadIdx.y;
    #pragma unroll
    for (int j = 0; j < 32; j += 8)
        t[ty+j][tx] = W[(size_t)(bn+ty+j)*FEAT + bk + tx];
    __syncthreads();
    #pragma unroll
    for (int j = 0; j < 32; j += 8)
        Wt[(size_t)(bk+ty+j)*FEAT + bn + tx] = tf32r(t[tx][ty+j]);
}

// mode = blockIdx.x & 1 : 0 = down path (gather-sum -> H_new), 1 = up path (H_down -> 4x fanout)
// 0.5 adjacency weight dropped (LayerNorm is invariant to uniform row scale).
__global__ __launch_bounds__(THREADS, 3)
void fused(const float* __restrict__ Ho, const float* __restrict__ Hd,
           const float* __restrict__ g0v, const float* __restrict__ b0v,
           const float* __restrict__ g1v, const float* __restrict__ b1v,
           float* __restrict__ outbase)
{
    extern __shared__ float sm[];
    float*  Asm  = sm;
    float*  Wsm  = sm + OFF_W;
    float*  gs   = sm + OFF_G;
    float*  bs   = sm + OFF_B;
    float2* red2 = (float2*)(sm + OFF_RED);

    const int tid  = threadIdx.x;
    const int lane = tid & 31;
    const int w    = tid >> 5;
    const int rg   = w & 1;        // 32-row group
    const int ch   = w >> 1;       // 64-col quarter (0..3)
    const int ly   = lane >> 2;
    const int kq   = lane & 3;

    const int mode = blockIdx.x & 1;
    const int tile = blockIdx.x >> 1;      // 0..1023
    const int b    = tile >> 8;
    const int rem  = tile & 255;
    const int di   = rem >> 1;
    const int half = rem & 1;

    {
        const float* gv = mode ? g1v : g0v;
        const float* bv = mode ? b1v : b0v;
        gs[tid] = gv[tid]; bs[tid] = bv[tid];
    }

    const float* Wt = Wt_dev[mode];
    const uint32_t smb = (uint32_t)__cvta_generic_to_shared(sm);

    float acc[2][8][4];
    #pragma unroll
    for (int t2 = 0; t2 < 2; t2++)
        #pragma unroll
        for (int nt = 0; nt < 8; nt++)
            #pragma unroll
            for (int e = 0; e < 4; e++) acc[t2][nt][e] = 0.f;

    // per-thread A coords: 64 rows x 4 float4 per chunk -> 1 float4/thread
    const int dj = tid >> 2, q = tid & 3;
    const size_t orow = (size_t)b*NORIG + (size_t)(2*di)*ORIG_ + (size_t)2*(half*64 + dj);
    const size_t drow = (size_t)b*NDOWN + (size_t)(di*DOWN_ + half*64 + dj);

    // ---- loaders ----
    auto loadW = [&](int kc, int sl){
        const float* src = Wt + (size_t)(kc*KCH)*FEAT;
        uint32_t base = smb + 4u*(OFF_W + sl*W_BUF);
        #pragma unroll
        for (int it = 0; it < 4; it++){
            int idx = tid + it*THREADS;          // 0..1023 float4
            int k = idx >> 6, n4 = idx & 63;
            cpasync16(base + 4u*(k*W_STRIDE + n4*4), src + (size_t)k*FEAT + n4*4);
        }
    };
    auto loadA1 = [&](int kc, int sl){   // mode 1: direct cp.async
        cpasync16(smb + 4u*(sl*A_BUF + dj*A_STRIDE + q*4),
                  Hd + drow*FEAT + kc*KCH + q*4);
    };
    float4 p0, p1, p2, p3;       // mode 0 pending gather regs (live across ONE barrier only)
    auto issueA0 = [&](int kc){
        const float4* p = (const float4*)Ho + orow*64 + kc*4 + q;
        p0 = __ldcs(p);
        p1 = __ldcs(p + 64);
        p2 = __ldcs(p + ORIG_*64);
        p3 = __ldcs(p + ORIG_*64 + 64);
    };
    auto finishA0 = [&](int sl){
        float4 s;
        s.x = tf32r((p0.x+p1.x)+(p2.x+p3.x));
        s.y = tf32r((p0.y+p1.y)+(p2.y+p3.y));
        s.z = tf32r((p0.z+p1.z)+(p2.z+p3.z));
        s.w = tf32r((p0.w+p1.w)+(p2.w+p3.w));
        *(float4*)&Asm[sl*A_BUF + dj*A_STRIDE + q*4] = s;
    };

    // ---- prologue: W chunks 0,1 in flight; mode0 chunk-0 LDGs pending ----
    if (mode == 0) issueA0(0);
    loadW(0, 0); if (mode) loadA1(0, 0); cpcommit();
    loadW(1, 1); if (mode) loadA1(1, 1); cpcommit();

    // ---- 3-stage pipelined mainloop ----
    int sl = 0, sl2 = 2;   // slot of chunk c, slot of chunk c+2
    for (int c = 0; c < NCHUNK; c++){
        if (c < NCHUNK-1) cpwait1(); else cpwait0();
        __syncthreads();

        if (mode == 0) finishA0(sl);           // STS A(c); pending regs now free
        if (c+2 < NCHUNK){
            loadW(c+2, sl2);
            if (mode) loadA1(c+2, sl2);
            cpcommit();
        }
        if (mode == 0) __syncthreads();        // A(c) visible to all warps

        const float* Ab = Asm + sl*A_BUF;
        const float* Wb = Wsm + sl*W_BUF;
        #pragma unroll
        for (int ks = 0; ks < 2; ks++){
            const int kk = ks*8;
            const int r0 = rg*32 + ly;
            uint32_t a0 = __float_as_uint(Ab[(r0    )*A_STRIDE + kk+kq  ]);
            uint32_t a1 = __float_as_uint(Ab[(r0+ 8 )*A_STRIDE + kk+kq  ]);
            uint32_t a2 = __float_as_uint(Ab[(r0    )*A_STRIDE + kk+kq+4]);
            uint32_t a3 = __float_as_uint(Ab[(r0+ 8 )*A_STRIDE + kk+kq+4]);
            uint32_t a4 = __float_as_uint(Ab[(r0+16 )*A_STRIDE + kk+kq  ]);
            uint32_t a5 = __float_as_uint(Ab[(r0+24 )*A_STRIDE + kk+kq  ]);
            uint32_t a6 = __float_as_uint(Ab[(r0+16 )*A_STRIDE + kk+kq+4]);
            uint32_t a7 = __float_as_uint(Ab[(r0+24 )*A_STRIDE + kk+kq+4]);
            #pragma unroll
            for (int nt = 0; nt < 8; nt++){
                const int n = ch*64 + nt*8 + ly;
                uint32_t bb0 = __float_as_uint(Wb[(kk+kq  )*W_STRIDE + n]);
                uint32_t bb1 = __float_as_uint(Wb[(kk+kq+4)*W_STRIDE + n]);
                mma8(acc[0][nt], a0, a1, a2, a3, bb0, bb1);
                mma8(acc[1][nt], a4, a5, a6, a7, bb0, bb1);
            }
        }

        if (mode == 0 && c+1 < NCHUNK) issueA0(c+1);   // LDGs overlap next wait+sync
        sl  = (sl  == 2) ? 0 : sl  + 1;
        sl2 = (sl2 == 2) ? 0 : sl2 + 1;
    }

    // ---- LayerNorm stats (4 rows per thread) ----
    const int rr0 = rg*32 + ly;
    float s[4] = {0.f,0.f,0.f,0.f}, qs[4] = {0.f,0.f,0.f,0.f};
    #pragma unroll
    for (int t2 = 0; t2 < 2; t2++)
        #pragma unroll
        for (int nt = 0; nt < 8; nt++){
            float x0=acc[t2][nt][0], x1=acc[t2][nt][1];
            float x2=acc[t2][nt][2], x3=acc[t2][nt][3];
            s[2*t2]   += x0+x1;  qs[2*t2]   += x0*x0 + x1*x1;
            s[2*t2+1] += x2+x3;  qs[2*t2+1] += x2*x2 + x3*x3;
        }
    #pragma unroll
    for (int o = 1; o < 4; o <<= 1)
        #pragma unroll
        for (int j = 0; j < 4; j++){
            s[j]  += __shfl_xor_sync(0xffffffffu, s[j],  o);
            qs[j] += __shfl_xor_sync(0xffffffffu, qs[j], o);
        }
    if (kq == 0){
        red2[ch*64 + rr0     ] = make_float2(s[0], qs[0]);
        red2[ch*64 + rr0 + 8 ] = make_float2(s[1], qs[1]);
        red2[ch*64 + rr0 + 16] = make_float2(s[2], qs[2]);
        red2[ch*64 + rr0 + 24] = make_float2(s[3], qs[3]);
    }
    __syncthreads();   // mainloop complete -> pipeline buffers reusable as staging

    float mean[4], rstd[4];
    #pragma unroll
    for (int j = 0; j < 4; j++){
        int row = rr0 + j*8;
        float ss = 0.f, qq = 0.f;
        #pragma unroll
        for (int p = 0; p < 4; p++){
            float2 pr = red2[p*64 + row];
            ss += pr.x; qq += pr.y;
        }
        mean[j] = ss * (1.f/FEAT);
        rstd[j] = rsqrtf(fmaxf(qq*(1.f/FEAT) - mean[j]*mean[j], 0.f) + 1e-5f);
    }

    // ---- stage normalized tile (64 x ST_STRIDE at sm[0]) ----
    float* st = sm;
    #pragma unroll
    for (int t2 = 0; t2 < 2; t2++)
        #pragma unroll
        for (int nt = 0; nt < 8; nt++){
            int col = ch*64 + nt*8 + 2*kq;
            float gg0 = gs[col], gg1 = gs[col+1], dd0 = bs[col], dd1 = bs[col+1];
            int jl = 2*t2, jh = 2*t2+1;
            int rl = rr0 + (t2?16:0), rh = rl + 8;
            float2 va, vb;
            va.x = fmaxf(fmaf((acc[t2][nt][0]-mean[jl])*rstd[jl], gg0, dd0), 0.f);
            va.y = fmaxf(fmaf((acc[t2][nt][1]-mean[jl])*rstd[jl], gg1, dd1), 0.f);
            vb.x = fmaxf(fmaf((acc[t2][nt][2]-mean[jh])*rstd[jh], gg0, dd0), 0.f);
            vb.y = fmaxf(fmaf((acc[t2][nt][3]-mean[jh])*rstd[jh], gg1, dd1), 0.f);
            *(float2*)&st[rl*ST_STRIDE + col] = va;
            *(float2*)&st[rh*ST_STRIDE + col] = vb;
        }
    __syncthreads();

    // ---- coalesced streaming stores ----
    float* out_orig = outbase;
    float* out_new  = outbase + (size_t)BATCH*NORIG*FEAT;
    if (mode == 0){
        float* dst = out_new + ((size_t)b*NDOWN + (size_t)(di*DOWN_ + half*64))*FEAT;
        #pragma unroll
        for (int j = 0; j < 16; j++){
            int i = tid + j*THREADS;            // 0..4095
            int row = i >> 6, c4 = i & 63;
            float4 v = *(float4*)&st[row*ST_STRIDE + c4*4];
            __stcs((float4*)(dst + row*FEAT + c4*4), v);
        }
    } else {
        const size_t nb = (size_t)b*NORIG;
        #pragma unroll
        for (int j = 0; j < 64; j++){
            int i = tid + j*THREADS;            // 0..16383
            int row = i >> 8;                   // src row 0..63
            int seg = (i >> 7) & 1;             // which orig grid row of the pair
            int off = i & 127;                  // float4 within 2048B dest segment
            int djg = half*64 + row;
            size_t dr = nb + (size_t)(2*di + seg)*ORIG_ + (size_t)2*djg;
            float4 v = *(float4*)&st[row*ST_STRIDE + (off & 63)*4];
            __stcs((float4*)(out_orig + dr*FEAT + off*4), v);
        }
    }
}

extern "C" void kernel_launch(void* const* d_in, const int* in_sizes, int n_in,
                              void* d_out, int out_size)
{
    const float* H_orig = (const float*)d_in[0];
    const float* H_down = (const float*)d_in[1];
    const float* W_o2n  = (const float*)d_in[2];
    const float* W_n2o  = (const float*)d_in[3];
    const float* g_o2n  = (const float*)d_in[4];
    const float* b_o2n  = (const float*)d_in[5];
    const float* g_n2o  = (const float*)d_in[6];
    const float* b_n2o  = (const float*)d_in[7];

    cudaFuncSetAttribute(fused, cudaFuncAttributeMaxDynamicSharedMemorySize, SM_BYTES);

    prep_w<<<dim3(8,8,2), dim3(32,8)>>>(W_o2n, W_n2o);
    fused<<<2048, THREADS, SM_BYTES>>>(H_orig, H_down,
                                       g_o2n, b_o2n, g_n2o, b_n2o,
                                       (float*)d_out);
}

// round 16
// speedup vs baseline: 2.3415x; 2.3415x over previous
#include <cuda_runtime.h>
#include <cstdint>

#define BATCH   4
#define ORIG_   256
#define NORIG   (ORIG_*ORIG_)     // 65536
#define DOWN_   128
#define NDOWN   (DOWN_*DOWN_)     // 16384
#define FEAT    256
#define TILE_M  64
#define THREADS 256
#define KCH     16
#define NCHUNK  16
#define STAGES  4

// SMEM layout (floats)
#define A_STRIDE 20
#define W_STRIDE 264
#define A_BUF    (TILE_M*A_STRIDE)        // 1280
#define W_BUF    (KCH*W_STRIDE)           // 4224
#define OFF_W    (STAGES*A_BUF)           // 5120
#define OFF_G    (OFF_W + STAGES*W_BUF)   // 22016
#define OFF_B    (OFF_G + FEAT)           // 22272
#define OFF_RED  (OFF_B + FEAT)           // 22528 (4*64 float2)
#define SM_FLOATS (OFF_RED + 512)         // 23040
#define SM_BYTES  (SM_FLOATS*4)           // 92160 -> 2 CTAs/SM
#define ST_STRIDE 264                     // epilogue staging (64x264 at sm[0] < OFF_G)

__device__ float Wt_dev[2][FEAT*FEAT];   // tf32-rounded, k-major weights

__device__ __forceinline__ float tf32r(float x){
    float r; asm("cvt.rna.tf32.f32 %0, %1;" : "=f"(r) : "f"(x)); return r;
}
__device__ __forceinline__ void cpasync16(uint32_t dst, const void* src){
    asm volatile("cp.async.cg.shared.global [%0], [%1], 16;\n" :: "r"(dst), "l"(src));
}
__device__ __forceinline__ void cpcommit(){ asm volatile("cp.async.commit_group;\n" ::: "memory"); }
__device__ __forceinline__ void cpwait0(){ asm volatile("cp.async.wait_group 0;\n" ::: "memory"); }
__device__ __forceinline__ void cpwait2(){ asm volatile("cp.async.wait_group 2;\n" ::: "memory"); }

__device__ __forceinline__ void mma8(float* c, uint32_t a0, uint32_t a1, uint32_t a2,
                                     uint32_t a3, uint32_t b0, uint32_t b1){
    asm volatile(
        "mma.sync.aligned.m16n8k8.row.col.f32.tf32.tf32.f32 "
        "{%0,%1,%2,%3}, {%4,%5,%6,%7}, {%8,%9}, {%0,%1,%2,%3};\n"
        : "+f"(c[0]), "+f"(c[1]), "+f"(c[2]), "+f"(c[3])
        : "r"(a0), "r"(a1), "r"(a2), "r"(a3), "r"(b0), "r"(b1));
}

// ---- prep: Wt[k][n] = tf32_rn(W[n][k]) (512 KB total; L2-resident) ----
__global__ void prep_w(const float* __restrict__ W0, const float* __restrict__ W1){
    __shared__ float t[32][33];
    const float* W  = blockIdx.z ? W1 : W0;
    float*       Wt = Wt_dev[blockIdx.z];
    int bk = blockIdx.x*32, bn = blockIdx.y*32;
    int tx = threadIdx.x, ty = threadIdx.y;
    #pragma unroll
    for (int j = 0; j < 32; j += 8)
        t[ty+j][tx] = W[(size_t)(bn+ty+j)*FEAT + bk + tx];
    __syncthreads();
    #pragma unroll
    for (int j = 0; j < 32; j += 8)
        Wt[(size_t)(bk+ty+j)*FEAT + bn + tx] = tf32r(t[tx][ty+j]);
}

// mode = blockIdx.x & 1 : 0 = down path (gather-sum -> H_new), 1 = up path (H_down -> 4x fanout)
// 0.5 adjacency weight dropped (LayerNorm is invariant to uniform row scale).
__global__ __launch_bounds__(THREADS, 2)
void fused(const float* __restrict__ Ho, const float* __restrict__ Hd,
           const float* __restrict__ g0v, const float* __restrict__ b0v,
           const float* __restrict__ g1v, const float* __restrict__ b1v,
           float* __restrict__ outbase)
{
    extern __shared__ float sm[];
    float*  Asm  = sm;
    float*  Wsm  = sm + OFF_W;
    float*  gs   = sm + OFF_G;
    float*  bs   = sm + OFF_B;
    float2* red2 = (float2*)(sm + OFF_RED);

    const int tid  = threadIdx.x;
    const int lane = tid & 31;
    const int w    = tid >> 5;
    const int rg   = w & 1;        // 32-row group
    const int ch   = w >> 1;       // 64-col quarter (0..3)
    const int ly   = lane >> 2;
    const int kq   = lane & 3;

    const int mode = blockIdx.x & 1;
    const int tile = blockIdx.x >> 1;      // 0..1023
    const int b    = tile >> 8;
    const int rem  = tile & 255;
    const int di   = rem >> 1;
    const int half = rem & 1;

    {
        const float* gv = mode ? g1v : g0v;
        const float* bv = mode ? b1v : b0v;
        gs[tid] = gv[tid]; bs[tid] = bv[tid];
    }

    const float* Wt = Wt_dev[mode];
    const uint32_t smb = (uint32_t)__cvta_generic_to_shared(sm);

    float acc[2][8][4];
    #pragma unroll
    for (int t2 = 0; t2 < 2; t2++)
        #pragma unroll
        for (int nt = 0; nt < 8; nt++)
            #pragma unroll
            for (int e = 0; e < 4; e++) acc[t2][nt][e] = 0.f;

    // per-thread A coords: 64 rows x 4 float4 per chunk -> 1 float4/thread
    const int dj = tid >> 2, q = tid & 3;
    const size_t orow = (size_t)b*NORIG + (size_t)(2*di)*ORIG_ + (size_t)2*(half*64 + dj);
    const size_t drow = (size_t)b*NDOWN + (size_t)(di*DOWN_ + half*64 + dj);

    // ---- loaders ----
    auto loadW = [&](int kc){
        const float* src = Wt + (size_t)(kc*KCH)*FEAT;
        uint32_t base = smb + 4u*(OFF_W + (kc&3)*W_BUF);
        #pragma unroll
        for (int it = 0; it < 4; it++){
            int idx = tid + it*THREADS;          // 0..1023 float4
            int k = idx >> 6, n4 = idx & 63;
            cpasync16(base + 4u*(k*W_STRIDE + n4*4), src + (size_t)k*FEAT + n4*4);
        }
    };
    auto loadA1 = [&](int kc){   // mode 1: direct cp.async
        cpasync16(smb + 4u*((kc&3)*A_BUF + dj*A_STRIDE + q*4),
                  Hd + drow*FEAT + kc*KCH + q*4);
    };
    float4 p0, p1, p2, p3;       // mode 0 pending gather registers
    auto issueA0 = [&](int kc){
        const float4* p = (const float4*)Ho + orow*64 + kc*4 + q;
        p0 = __ldcs(p);
        p1 = __ldcs(p + 64);
        p2 = __ldcs(p + ORIG_*64);
        p3 = __ldcs(p + ORIG_*64 + 64);
    };
    auto finishA0 = [&](int kc){
        float4 s;
        s.x = tf32r((p0.x+p1.x)+(p2.x+p3.x));
        s.y = tf32r((p0.y+p1.y)+(p2.y+p3.y));
        s.z = tf32r((p0.z+p1.z)+(p2.z+p3.z));
        s.w = tf32r((p0.w+p1.w)+(p2.w+p3.w));
        *(float4*)&Asm[(kc&3)*A_BUF + dj*A_STRIDE + q*4] = s;
    };

    // ---- prologue: chunks 0..2 in flight, mode0 chunk2 pending in regs ----
    if (mode == 0){
        issueA0(0); finishA0(0);
        issueA0(1); finishA0(1);
    }
    loadW(0); if (mode) loadA1(0); cpcommit();
    loadW(1); if (mode) loadA1(1); cpcommit();
    loadW(2); if (mode) loadA1(2); cpcommit();
    if (mode == 0) issueA0(2);
    __syncthreads();

    // ---- 4-stage pipelined mainloop ----
    for (int c = 0; c < NCHUNK; c++){
        if (c < NCHUNK-2) cpwait2(); else cpwait0();
        __syncthreads();

        if (mode == 0 && c+2 < NCHUNK) finishA0(c+2);
        if (c+3 < NCHUNK){
            loadW(c+3);
            if (mode) loadA1(c+3);
            cpcommit();
            if (mode == 0) issueA0(c+3);
        }

        const float* Ab = Asm + (c&3)*A_BUF;
        const float* Wb = Wsm + (c&3)*W_BUF;
        #pragma unroll
        for (int ks = 0; ks < 2; ks++){
            const int kk = ks*8;
            const int r0 = rg*32 + ly;
            uint32_t a0 = __float_as_uint(Ab[(r0    )*A_STRIDE + kk+kq  ]);
            uint32_t a1 = __float_as_uint(Ab[(r0+ 8 )*A_STRIDE + kk+kq  ]);
            uint32_t a2 = __float_as_uint(Ab[(r0    )*A_STRIDE + kk+kq+4]);
            uint32_t a3 = __float_as_uint(Ab[(r0+ 8 )*A_STRIDE + kk+kq+4]);
            uint32_t a4 = __float_as_uint(Ab[(r0+16 )*A_STRIDE + kk+kq  ]);
            uint32_t a5 = __float_as_uint(Ab[(r0+24 )*A_STRIDE + kk+kq  ]);
            uint32_t a6 = __float_as_uint(Ab[(r0+16 )*A_STRIDE + kk+kq+4]);
            uint32_t a7 = __float_as_uint(Ab[(r0+24 )*A_STRIDE + kk+kq+4]);
            #pragma unroll
            for (int nt = 0; nt < 8; nt++){
                const int n = ch*64 + nt*8 + ly;
                uint32_t bb0 = __float_as_uint(Wb[(kk+kq  )*W_STRIDE + n]);
                uint32_t bb1 = __float_as_uint(Wb[(kk+kq+4)*W_STRIDE + n]);
                mma8(acc[0][nt], a0, a1, a2, a3, bb0, bb1);
                mma8(acc[1][nt], a4, a5, a6, a7, bb0, bb1);
            }
        }
    }

    // ---- LayerNorm stats (4 rows per thread) ----
    const int rr0 = rg*32 + ly;
    float s[4] = {0.f,0.f,0.f,0.f}, qs[4] = {0.f,0.f,0.f,0.f};
    #pragma unroll
    for (int t2 = 0; t2 < 2; t2++)
        #pragma unroll
        for (int nt = 0; nt < 8; nt++){
            float x0=acc[t2][nt][0], x1=acc[t2][nt][1];
            float x2=acc[t2][nt][2], x3=acc[t2][nt][3];
            s[2*t2]   += x0+x1;  qs[2*t2]   += x0*x0 + x1*x1;
            s[2*t2+1] += x2+x3;  qs[2*t2+1] += x2*x2 + x3*x3;
        }
    #pragma unroll
    for (int o = 1; o < 4; o <<= 1)
        #pragma unroll
        for (int j = 0; j < 4; j++){
            s[j]  += __shfl_xor_sync(0xffffffffu, s[j],  o);
            qs[j] += __shfl_xor_sync(0xffffffffu, qs[j], o);
        }
    if (kq == 0){
        red2[ch*64 + rr0     ] = make_float2(s[0], qs[0]);
        red2[ch*64 + rr0 + 8 ] = make_float2(s[1], qs[1]);
        red2[ch*64 + rr0 + 16] = make_float2(s[2], qs[2]);
        red2[ch*64 + rr0 + 24] = make_float2(s[3], qs[3]);
    }
    __syncthreads();   // mainloop complete -> pipeline buffers reusable as staging

    float mean[4], rstd[4];
    #pragma unroll
    for (int j = 0; j < 4; j++){
        int row = rr0 + j*8;
        float ss = 0.f, qq = 0.f;
        #pragma unroll
        for (int p = 0; p < 4; p++){
            float2 pr = red2[p*64 + row];
            ss += pr.x; qq += pr.y;
        }
        mean[j] = ss * (1.f/FEAT);
        rstd[j] = rsqrtf(fmaxf(qq*(1.f/FEAT) - mean[j]*mean[j], 0.f) + 1e-5f);
    }

    // ---- stage normalized tile (64 x ST_STRIDE at sm[0]) ----
    float* st = sm;
    #pragma unroll
    for (int t2 = 0; t2 < 2; t2++)
        #pragma unroll
        for (int nt = 0; nt < 8; nt++){
            int col = ch*64 + nt*8 + 2*kq;
            float gg0 = gs[col], gg1 = gs[col+1], dd0 = bs[col], dd1 = bs[col+1];
            int jl = 2*t2, jh = 2*t2+1;
            int rl = rr0 + (t2?16:0), rh = rl + 8;
            float2 va, vb;
            va.x = fmaxf(fmaf((acc[t2][nt][0]-mean[jl])*rstd[jl], gg0, dd0), 0.f);
            va.y = fmaxf(fmaf((acc[t2][nt][1]-mean[jl])*rstd[jl], gg1, dd1), 0.f);
            vb.x = fmaxf(fmaf((acc[t2][nt][2]-mean[jh])*rstd[jh], gg0, dd0), 0.f);
            vb.y = fmaxf(fmaf((acc[t2][nt][3]-mean[jh])*rstd[jh], gg1, dd1), 0.f);
            *(float2*)&st[rl*ST_STRIDE + col] = va;
            *(float2*)&st[rh*ST_STRIDE + col] = vb;
        }
    __syncthreads();

    // ---- coalesced streaming stores ----
    float* out_orig = outbase;
    float* out_new  = outbase + (size_t)BATCH*NORIG*FEAT;
    if (mode == 0){
        float* dst = out_new + ((size_t)b*NDOWN + (size_t)(di*DOWN_ + half*64))*FEAT;
        #pragma unroll
        for (int j = 0; j < 16; j++){
            int i = tid + j*THREADS;            // 0..4095
            int row = i >> 6, c4 = i & 63;
            float4 v = *(float4*)&st[row*ST_STRIDE + c4*4];
            __stcs((float4*)(dst + row*FEAT + c4*4), v);
        }
    } else {
        // read staging ONCE per float4, write 4 fanout copies from registers
        const size_t nb = (size_t)b*NORIG;
        #pragma unroll
        for (int j = 0; j < 16; j++){
            int i = tid + j*THREADS;            // 0..4095
            int row = i >> 6, c4 = i & 63;      // src row 0..63, float4 col 0..63
            int djg = half*64 + row;
            float4 v = *(float4*)&st[row*ST_STRIDE + c4*4];
            float* d0 = out_orig + (nb + (size_t)(2*di)*ORIG_ + (size_t)2*djg)*FEAT + c4*4;
            __stcs((float4*)(d0                    ), v);
            __stcs((float4*)(d0 + FEAT             ), v);
            __stcs((float4*)(d0 + ORIG_*FEAT       ), v);
            __stcs((float4*)(d0 + ORIG_*FEAT + FEAT), v);
        }
    }
}

extern "C" void kernel_launch(void* const* d_in, const int* in_sizes, int n_in,
                              void* d_out, int out_size)
{
    const float* H_orig = (const float*)d_in[0];
    const float* H_down = (const float*)d_in[1];
    const float* W_o2n  = (const float*)d_in[2];
    const float* W_n2o  = (const float*)d_in[3];
    const float* g_o2n  = (const float*)d_in[4];
    const float* b_o2n  = (const float*)d_in[5];
    const float* g_n2o  = (const float*)d_in[6];
    const float* b_n2o  = (const float*)d_in[7];

    cudaFuncSetAttribute(fused, cudaFuncAttributeMaxDynamicSharedMemorySize, SM_BYTES);

    prep_w<<<dim3(8,8,2), dim3(32,8)>>>(W_o2n, W_n2o);
    fused<<<2048, THREADS, SM_BYTES>>>(H_orig, H_down,
                                       g_o2n, b_o2n, g_n2o, b_n2o,
                                       (float*)d_out);
}